// round 11
// baseline (speedup 1.0000x reference)
#include <cuda_runtime.h>
#include <cuda_bf16.h>

#define N_NODES 384
#define HEIGHT  60
#define CCH     128
#define N_LAYERS 4
#define NODE_SZ (CCH * HEIGHT)          // 7680 floats per node
#define NODE_BYTES (NODE_SZ * 4)        // 30720
#define ES_OFF  (3 * NODE_SZ)
#define DYN_F   (ES_OFF + 8 * CCH)
#define DYN_SMEM (DYN_F * 4)            // ~94 KB (fused kernel)
#define G0_SMEM ((NODE_SZ + 8192 * 2) * 4)

// ---------------- device scratch ----------------
// DOUBLE-BUFFERED: fused launch l reads buf l&1, writes buf (l+1)&1
__device__ __align__(16) float g_y[2][N_NODES * 2 * NODE_SZ];
// A fragments (bf16 hi/lo): [l][mt16][ks8][lane32][4regs] u32
__device__ __align__(16) unsigned WFh[N_LAYERS * 16384];
__device__ __align__(16) unsigned WFl[N_LAYERS * 16384];
__device__ float g_M[N_LAYERS * CCH * 6];
__device__ int   g_nbr[N_NODES * 16];
__device__ int   g_deg[N_NODES];

// ---------------- helpers ----------------
__device__ __forceinline__ unsigned pack_bf16x2(float a, float b) {
    __nv_bfloat162 p = __floats2bfloat162_rn(a, b);
    return *reinterpret_cast<unsigned*>(&p);
}
__device__ __forceinline__ void mma16816(float* d, const uint4& a, const uint2& b) {
    asm volatile(
        "mma.sync.aligned.m16n8k16.row.col.f32.bf16.bf16.f32 "
        "{%0,%1,%2,%3}, {%4,%5,%6,%7}, {%8,%9}, {%0,%1,%2,%3};"
        : "+f"(d[0]), "+f"(d[1]), "+f"(d[2]), "+f"(d[3])
        : "r"(a.x), "r"(a.y), "r"(a.z), "r"(a.w), "r"(b.x), "r"(b.y));
}
__device__ __forceinline__ void mbar_init(unsigned mbar, unsigned count) {
    asm volatile("mbarrier.init.shared.b64 [%0], %1;" :: "r"(mbar), "r"(count) : "memory");
}
__device__ __forceinline__ void mbar_expect_tx(unsigned mbar, unsigned bytes) {
    asm volatile("mbarrier.arrive.expect_tx.shared.b64 _, [%0], %1;"
                 :: "r"(mbar), "r"(bytes) : "memory");
}
__device__ __forceinline__ void tma_bulk_g2s(unsigned sdst, const void* gsrc,
                                             unsigned bytes, unsigned mbar) {
    asm volatile(
        "cp.async.bulk.shared::cluster.global.mbarrier::complete_tx::bytes "
        "[%0], [%1], %2, [%3];"
        :: "r"(sdst), "l"(gsrc), "r"(bytes), "r"(mbar) : "memory");
}
__device__ __forceinline__ void mbar_wait(unsigned mbar, unsigned parity) {
    asm volatile(
        "{\n\t.reg .pred P;\n"
        "WAIT_%=:\n\t"
        "mbarrier.try_wait.parity.acquire.cta.shared::cta.b64 P, [%0], %1, 0x989680;\n\t"
        "@P bra WAIT_DONE_%=;\n\t"
        "bra.uni WAIT_%=;\n"
        "WAIT_DONE_%=:\n\t}"
        :: "r"(mbar), "r"(parity) : "memory");
}

// linear (c,h) smem buffer -> B fragments (hi/lo) in smem.
__device__ __forceinline__ void frag_convert(const float* lin, unsigned* FH, unsigned* FL, int tid) {
    for (int s = tid; s < 4096; s += 512) {
        int breg = s & 1, lane = (s >> 1) & 31, nf = (s >> 6) & 7, ks = s >> 9;
        int c0 = ks * 16 + breg * 8 + (lane & 3) * 2;
        int h = nf * 8 + (lane >> 2);
        float v0 = 0.f, v1 = 0.f;
        if (h < HEIGHT) {
            v0 = lin[c0 * HEIGHT + h];
            v1 = lin[(c0 + 1) * HEIGHT + h];
        }
        float h0 = __bfloat162float(__float2bfloat16(v0));
        float h1 = __bfloat162float(__float2bfloat16(v1));
        FH[s] = pack_bf16x2(h0, h1);
        FL[s] = pack_bf16x2(v0 - h0, v1 - h1);
    }
}

// full-node MMA: 16 warps x 1 mtile; B frags from smem, A frags from global (L1).
__device__ __forceinline__ void mma_node(const unsigned* FH, const unsigned* FL,
                                         int l, int node, int tid,
                                         float* __restrict__ yout) {
    int w = tid >> 5, lane = tid & 31;
    int g = lane >> 2, t = lane & 3;
    const uint4* WAh = reinterpret_cast<const uint4*>(WFh);
    const uint4* WAl = reinterpret_cast<const uint4*>(WFl);

#pragma unroll
    for (int half = 0; half < 2; half++) {
        float acc[4][4];
#pragma unroll
        for (int nf = 0; nf < 4; nf++)
#pragma unroll
            for (int q = 0; q < 4; q++) acc[nf][q] = 0.f;

#pragma unroll
        for (int ks = 0; ks < 8; ks++) {
            int ai = ((l * 16 + w) * 8 + ks) * 32 + lane;
            uint4 Ah = __ldg(WAh + ai);
            uint4 Al = __ldg(WAl + ai);
#pragma unroll
            for (int nf = 0; nf < 4; nf++) {
                int s = ks * 512 + (half * 4 + nf) * 64 + lane * 2;
                uint2 Bh = *reinterpret_cast<const uint2*>(FH + s);
                uint2 Bl = *reinterpret_cast<const uint2*>(FL + s);
                mma16816(acc[nf], Ah, Bh);
                mma16816(acc[nf], Ah, Bl);
                mma16816(acc[nf], Al, Bh);
            }
        }
#pragma unroll
        for (int nf = 0; nf < 4; nf++) {
            int m = w * 16 + g;
            int h0 = (half * 4 + nf) * 8 + 2 * t;
            if (h0 < HEIGHT) {
                size_t base = ((size_t)node * 2 + (m >> 7)) * NODE_SZ;
                float* p0 = yout + base + (m & 127) * HEIGHT + h0;
                *(float2*)p0 = make_float2(acc[nf][0], acc[nf][1]);
                float* p1 = yout + base + ((m + 8) & 127) * HEIGHT + h0;
                *(float2*)p1 = make_float2(acc[nf][2], acc[nf][3]);
            }
        }
    }
}

// ---------------- setup: blk0 = CSR, blk1..4 = weight frags + M ---------------
__global__ void setup_kernel(const int* __restrict__ ei, int E,
                             const float* __restrict__ conv_w,
                             const float* __restrict__ edge_w,
                             const float* __restrict__ edge_b) {
    int tid = threadIdx.x;
    if (blockIdx.x == 0) {
        int n = tid;
        if (n >= N_NODES) return;
        const int* dst = ei + E;
        int cnt = 0;
        for (int e = 0; e < E; e++) {
            if (dst[e] == n) {
                if (cnt < 8) g_nbr[n * 16 + cnt] = e;
                cnt++;
            }
        }
        g_deg[n] = cnt < 8 ? cnt : 8;
        return;
    }
    int l = blockIdx.x - 1;
    const float* cw = conv_w + l * (CCH * 3 * CCH);
    for (int i = tid; i < 16384; i += 384) {
        int j = i & 3, lane = (i >> 2) & 31, ks = (i >> 7) & 7, mt = i >> 10;
        int g = lane >> 2, t = lane & 3;
        int m = (mt << 4) + g + ((j & 1) << 3);
        int k = (ks << 4) + (t << 1) + ((j >> 1) << 3);
        float v0, v1;
        if (m < 128) {
            v0 = cw[m * 384 + k] - cw[m * 384 + 128 + k];
            v1 = cw[m * 384 + k + 1] - cw[m * 384 + 128 + k + 1];
        } else {
            v0 = cw[(m - 128) * 384 + 128 + k];
            v1 = cw[(m - 128) * 384 + 128 + k + 1];
        }
        float h0 = __bfloat162float(__float2bfloat16(v0));
        float h1 = __bfloat162float(__float2bfloat16(v1));
        WFh[l * 16384 + i] = pack_bf16x2(h0, h1);
        WFl[l * 16384 + i] = pack_bf16x2(v0 - h0, v1 - h1);
    }
    if (tid < CCH) {
        int c = tid;
        const float* cw3 = cw + c * 384 + 256;
        const float* ewl = edge_w + l * (CCH * 5);
        const float* ebl = edge_b + l * CCH;
        float m0 = 0.f, m1 = 0.f, m2 = 0.f, m3 = 0.f, m4 = 0.f, m5 = 0.f;
        for (int k = 0; k < CCH; k++) {
            float w = cw3[k];
            m0 += w * ewl[k * 5 + 0];
            m1 += w * ewl[k * 5 + 1];
            m2 += w * ewl[k * 5 + 2];
            m3 += w * ewl[k * 5 + 3];
            m4 += w * ewl[k * 5 + 4];
            m5 += w * ebl[k];
        }
        float* Mp = g_M + l * (CCH * 6) + c * 6;
        Mp[0] = m0; Mp[1] = m1; Mp[2] = m2; Mp[3] = m3; Mp[4] = m4; Mp[5] = m5;
    }
}

// ---------------- G0: layer-0 GEMM, smem-resident -> buf 0 --------------------
__global__ __launch_bounds__(512, 2)
void gemm0_kernel(const float* __restrict__ x0) {
    extern __shared__ float sm[];
    float* lin = sm;
    unsigned* FH = reinterpret_cast<unsigned*>(sm + NODE_SZ);
    unsigned* FL = FH + 4096;
    int node = blockIdx.x, tid = threadIdx.x;
    const float* xn = x0 + (size_t)node * NODE_SZ;
#pragma unroll
    for (int it = 0; it < 15; it++)
        lin[tid + (it << 9)] = xn[tid + (it << 9)];
    __syncthreads();
    frag_convert(lin, FH, FL, tid);
    __syncthreads();
    mma_node(FH, FL, 0, node, tid, g_y[0]);
}

// ---------------- F_l: edge(l) [+ gemm(l+1) in-CTA], TMA-bulk ring ------------
__global__ __launch_bounds__(512, 2)
void fused_kernel(const float* __restrict__ ea,
                  const float* __restrict__ lng,
                  const float* __restrict__ lnb,
                  const int* __restrict__ ei,
                  float* __restrict__ dout, int l) {
    extern __shared__ float sm[];
    float* es_all = sm + ES_OFF;
    __shared__ float red[32];
    __shared__ __align__(8) unsigned long long mbar[3];

    int n = blockIdx.x, tid = threadIdx.x;
    const float* gl = lng + l * NODE_SZ;
    const float* bl = lnb + l * NODE_SZ;
    const float* ybuf = g_y[l & 1];
    int deg = g_deg[n];

    unsigned smem_base = (unsigned)__cvta_generic_to_shared(sm);
    unsigned mbar_base = (unsigned)__cvta_generic_to_shared(mbar);

    if (tid == 0) {
        mbar_init(mbar_base, 1);
        mbar_init(mbar_base + 8, 1);
        mbar_init(mbar_base + 16, 1);
    }
    __syncthreads();
    if (tid == 0) {   // prefetch edge 0 into slot 0 (one TMA bulk op)
        int s0 = ei[g_nbr[n * 16]];
        mbar_expect_tx(mbar_base, NODE_BYTES);
        tma_bulk_g2s(smem_base, ybuf + (size_t)(2 * s0 + 1) * NODE_SZ, NODE_BYTES, mbar_base);
    }

    const float* yan = ybuf + (size_t)(2 * n) * NODE_SZ;
    float ya[15], acc[15];
#pragma unroll
    for (int it = 0; it < 15; it++) {
        ya[it] = yan[tid + (it << 9)];
        acc[it] = 0.f;
    }
    for (int idx = tid; idx < deg * CCH; idx += 512) {
        int j = idx >> 7, c = idx & 127;
        int e = g_nbr[n * 16 + j];
        const float* Mp = g_M + l * (CCH * 6) + c * 6;
        const float* eap = ea + e * 5;
        es_all[idx] = fmaf(Mp[0], eap[0], fmaf(Mp[1], eap[1], fmaf(Mp[2], eap[2],
                      fmaf(Mp[3], eap[3], fmaf(Mp[4], eap[4], Mp[5])))));
    }

    for (int j = 0; j < deg; j++) {
        int bj = j % 3;
        __syncthreads();   // BARRIER_A: all threads done iter j-1 (es_all on j==0;
                           // red reuse; ring-slot (j+1)%3 readers finished)
        if (tid == 0 && j + 1 < deg) {
            int s1i = ei[g_nbr[n * 16 + j + 1]];
            int bn = (j + 1) % 3;
            mbar_expect_tx(mbar_base + 8 * bn, NODE_BYTES);
            tma_bulk_g2s(smem_base + bn * NODE_BYTES,
                         ybuf + (size_t)(2 * s1i + 1) * NODE_SZ, NODE_BYTES,
                         mbar_base + 8 * bn);
        }
        mbar_wait(mbar_base + 8 * bj, (j >= 3) ? 1u : 0u);

        const float* bf = sm + bj * NODE_SZ;
        const float* esj = es_all + j * CCH;
        float s1 = 0.f, s2 = 0.f;
#pragma unroll
        for (int it = 0; it < 15; it++) {
            int i = tid + (it << 9);
            float v = ya[it] + bf[i] + esj[i / HEIGHT];
            s1 += v;
            s2 += v * v;
        }
#pragma unroll
        for (int o = 16; o; o >>= 1) {
            s1 += __shfl_xor_sync(0xffffffffu, s1, o);
            s2 += __shfl_xor_sync(0xffffffffu, s2, o);
        }
        if ((tid & 31) == 0) { red[tid >> 5] = s1; red[16 + (tid >> 5)] = s2; }
        __syncthreads();   // BARRIER_B
        float a = 0.f, b2 = 0.f;
#pragma unroll
        for (int w = 0; w < 16; w++) { a += red[w]; b2 += red[16 + w]; }
        float mu = a * (1.f / (float)NODE_SZ);
        float rs = rsqrtf(b2 * (1.f / (float)NODE_SZ) - mu * mu + 1e-5f);
#pragma unroll
        for (int it = 0; it < 15; it++) {
            int i = tid + (it << 9);
            float v = ya[it] + bf[i] + esj[i / HEIGHT];
            float o2 = (v - mu) * rs * gl[i] + bl[i];
            acc[it] += fmaxf(o2, 0.f);
        }
    }

    if (l == 3) {
        float* on = dout + (size_t)n * NODE_SZ;
#pragma unroll
        for (int it = 0; it < 15; it++)
            on[tid + (it << 9)] = acc[it];
        return;
    }

    // ---- in-CTA gemm(l+1): acc -> lin -> B frags (smem) -> MMA -> buf (l+1)&1 -
    __syncthreads();              // all ring-slot reads complete
    float* lin = sm;
    unsigned* FH = reinterpret_cast<unsigned*>(sm + NODE_SZ);
    unsigned* FL = FH + 4096;
#pragma unroll
    for (int it = 0; it < 15; it++)
        lin[tid + (it << 9)] = acc[it];
    __syncthreads();
    frag_convert(lin, FH, FL, tid);
    __syncthreads();
    mma_node(FH, FL, l + 1, n, tid, g_y[(l + 1) & 1]);
}

// ---------------- launch -----------------------------------------------------
extern "C" void kernel_launch(void* const* d_in, const int* in_sizes, int n_in,
                              void* d_out, int out_size) {
    const float* x   = (const float*)d_in[0];
    const float* ea  = (const float*)d_in[1];
    const float* ew  = (const float*)d_in[2];
    const float* eb  = (const float*)d_in[3];
    const float* cw  = (const float*)d_in[4];
    const float* lng = (const float*)d_in[5];
    const float* lnb = (const float*)d_in[6];
    const int*   ei  = (const int*)d_in[7];
    float* out = (float*)d_out;
    int E = in_sizes[7] / 2;

    cudaFuncSetAttribute(gemm0_kernel, cudaFuncAttributeMaxDynamicSharedMemorySize, G0_SMEM);
    cudaFuncSetAttribute(fused_kernel, cudaFuncAttributeMaxDynamicSharedMemorySize, DYN_SMEM);

    setup_kernel<<<5, 384>>>(ei, E, cw, ew, eb);
    gemm0_kernel<<<N_NODES, 512, G0_SMEM>>>(x);
    for (int l = 0; l < N_LAYERS; l++)
        fused_kernel<<<N_NODES, 512, DYN_SMEM>>>(ea, lng, lnb, ei, out, l);
}

// round 12
// speedup vs baseline: 1.1731x; 1.1731x over previous
#include <cuda_runtime.h>
#include <cuda_bf16.h>

#define N_NODES 384
#define HEIGHT  60
#define CCH     128
#define N_LAYERS 4
#define NODE_SZ (CCH * HEIGHT)          // 7680 floats per node
// smem: lin [0, NODE_SZ) | FH [NODE_SZ, +4096u) | FL next. es_all aliases FH.
#define DYN_SMEM ((NODE_SZ + 8192) * 4)   // 62 KB -> 2 CTAs/SM

// ---------------- device scratch ----------------
// DOUBLE-BUFFERED: fused launch l reads buf l&1, writes buf (l+1)&1
__device__ __align__(16) float g_y[2][N_NODES * 2 * NODE_SZ];
// A fragments (bf16 hi/lo): [l][mt16][ks8][lane32][4regs] u32
__device__ __align__(16) unsigned WFh[N_LAYERS * 16384];
__device__ __align__(16) unsigned WFl[N_LAYERS * 16384];
__device__ float g_M[N_LAYERS * CCH * 6];
__device__ int   g_nbr[N_NODES * 16];
__device__ int   g_deg[N_NODES];
__device__ int   g_notok[N_LAYERS];     // 0 => ln_g==1 && ln_b==0 (fast path)

// ---------------- helpers ----------------
__device__ __forceinline__ unsigned pack_bf16x2(float a, float b) {
    __nv_bfloat162 p = __floats2bfloat162_rn(a, b);
    return *reinterpret_cast<unsigned*>(&p);
}
__device__ __forceinline__ void mma16816(float* d, const uint4& a, const uint2& b) {
    asm volatile(
        "mma.sync.aligned.m16n8k16.row.col.f32.bf16.bf16.f32 "
        "{%0,%1,%2,%3}, {%4,%5,%6,%7}, {%8,%9}, {%0,%1,%2,%3};"
        : "+f"(d[0]), "+f"(d[1]), "+f"(d[2]), "+f"(d[3])
        : "r"(a.x), "r"(a.y), "r"(a.z), "r"(a.w), "r"(b.x), "r"(b.y));
}

// linear (c,h) smem buffer -> B fragments (hi/lo) in smem.
__device__ __forceinline__ void frag_convert(const float* lin, unsigned* FH, unsigned* FL, int tid) {
    for (int s = tid; s < 4096; s += 512) {
        int breg = s & 1, lane = (s >> 1) & 31, nf = (s >> 6) & 7, ks = s >> 9;
        int c0 = ks * 16 + breg * 8 + (lane & 3) * 2;
        int h = nf * 8 + (lane >> 2);
        float v0 = 0.f, v1 = 0.f;
        if (h < HEIGHT) {
            v0 = lin[c0 * HEIGHT + h];
            v1 = lin[(c0 + 1) * HEIGHT + h];
        }
        float h0 = __bfloat162float(__float2bfloat16(v0));
        float h1 = __bfloat162float(__float2bfloat16(v1));
        FH[s] = pack_bf16x2(h0, h1);
        FL[s] = pack_bf16x2(v0 - h0, v1 - h1);
    }
}

// full-node MMA: 16 warps x 1 mtile; B frags from smem, A frags from global (L1).
__device__ __forceinline__ void mma_node(const unsigned* FH, const unsigned* FL,
                                         int l, int node, int tid,
                                         float* __restrict__ yout) {
    int w = tid >> 5, lane = tid & 31;
    int g = lane >> 2, t = lane & 3;
    const uint4* WAh = reinterpret_cast<const uint4*>(WFh);
    const uint4* WAl = reinterpret_cast<const uint4*>(WFl);

#pragma unroll
    for (int half = 0; half < 2; half++) {
        float acc[4][4];
#pragma unroll
        for (int nf = 0; nf < 4; nf++)
#pragma unroll
            for (int q = 0; q < 4; q++) acc[nf][q] = 0.f;

#pragma unroll
        for (int ks = 0; ks < 8; ks++) {
            int ai = ((l * 16 + w) * 8 + ks) * 32 + lane;
            uint4 Ah = __ldg(WAh + ai);
            uint4 Al = __ldg(WAl + ai);
#pragma unroll
            for (int nf = 0; nf < 4; nf++) {
                int s = ks * 512 + (half * 4 + nf) * 64 + lane * 2;
                uint2 Bh = *reinterpret_cast<const uint2*>(FH + s);
                uint2 Bl = *reinterpret_cast<const uint2*>(FL + s);
                mma16816(acc[nf], Ah, Bh);
                mma16816(acc[nf], Ah, Bl);
                mma16816(acc[nf], Al, Bh);
            }
        }
#pragma unroll
        for (int nf = 0; nf < 4; nf++) {
            int m = w * 16 + g;
            int h0 = (half * 4 + nf) * 8 + 2 * t;
            if (h0 < HEIGHT) {
                size_t base = ((size_t)node * 2 + (m >> 7)) * NODE_SZ;
                float* p0 = yout + base + (m & 127) * HEIGHT + h0;
                *(float2*)p0 = make_float2(acc[nf][0], acc[nf][1]);
                float* p1 = yout + base + ((m + 8) & 127) * HEIGHT + h0;
                *(float2*)p1 = make_float2(acc[nf][2], acc[nf][3]);
            }
        }
    }
}

// ---------------- setup: blk0 = CSR, blk1..4 = weight frags + M + LN check ----
__global__ void setup_kernel(const int* __restrict__ ei, int E,
                             const float* __restrict__ conv_w,
                             const float* __restrict__ edge_w,
                             const float* __restrict__ edge_b,
                             const float* __restrict__ lng,
                             const float* __restrict__ lnb) {
    int tid = threadIdx.x;
    if (blockIdx.x == 0) {
        int n = tid;
        if (n >= N_NODES) return;
        const int* dst = ei + E;
        int cnt = 0;
        for (int e = 0; e < E; e++) {
            if (dst[e] == n) {
                if (cnt < 8) g_nbr[n * 16 + cnt] = e;
                cnt++;
            }
        }
        g_deg[n] = cnt < 8 ? cnt : 8;
        return;
    }
    int l = blockIdx.x - 1;
    const float* cw = conv_w + l * (CCH * 3 * CCH);
    for (int i = tid; i < 16384; i += 384) {
        int j = i & 3, lane = (i >> 2) & 31, ks = (i >> 7) & 7, mt = i >> 10;
        int g = lane >> 2, t = lane & 3;
        int m = (mt << 4) + g + ((j & 1) << 3);
        int k = (ks << 4) + (t << 1) + ((j >> 1) << 3);
        float v0, v1;
        if (m < 128) {
            v0 = cw[m * 384 + k] - cw[m * 384 + 128 + k];
            v1 = cw[m * 384 + k + 1] - cw[m * 384 + 128 + k + 1];
        } else {
            v0 = cw[(m - 128) * 384 + 128 + k];
            v1 = cw[(m - 128) * 384 + 128 + k + 1];
        }
        float h0 = __bfloat162float(__float2bfloat16(v0));
        float h1 = __bfloat162float(__float2bfloat16(v1));
        WFh[l * 16384 + i] = pack_bf16x2(h0, h1);
        WFl[l * 16384 + i] = pack_bf16x2(v0 - h0, v1 - h1);
    }
    // LN trivial-params check (gl==1, bl==0 -> fast path)
    {
        const float* gl = lng + l * NODE_SZ;
        const float* bl = lnb + l * NODE_SZ;
        int bad = 0;
        for (int i = tid; i < NODE_SZ; i += 384)
            bad |= (gl[i] != 1.f) | (bl[i] != 0.f);
        if (bad) atomicOr(&g_notok[l], 1);
    }
    if (tid < CCH) {
        int c = tid;
        const float* cw3 = cw + c * 384 + 256;
        const float* ewl = edge_w + l * (CCH * 5);
        const float* ebl = edge_b + l * CCH;
        float m0 = 0.f, m1 = 0.f, m2 = 0.f, m3 = 0.f, m4 = 0.f, m5 = 0.f;
        for (int k = 0; k < CCH; k++) {
            float w = cw3[k];
            m0 += w * ewl[k * 5 + 0];
            m1 += w * ewl[k * 5 + 1];
            m2 += w * ewl[k * 5 + 2];
            m3 += w * ewl[k * 5 + 3];
            m4 += w * ewl[k * 5 + 4];
            m5 += w * ebl[k];
        }
        float* Mp = g_M + l * (CCH * 6) + c * 6;
        Mp[0] = m0; Mp[1] = m1; Mp[2] = m2; Mp[3] = m3; Mp[4] = m4; Mp[5] = m5;
    }
}

// ---------------- G0: layer-0 GEMM, smem-resident -> buf 0 --------------------
__global__ __launch_bounds__(512, 2)
void gemm0_kernel(const float* __restrict__ x0) {
    extern __shared__ float sm[];
    float* lin = sm;
    unsigned* FH = reinterpret_cast<unsigned*>(sm + NODE_SZ);
    unsigned* FL = FH + 4096;
    int node = blockIdx.x, tid = threadIdx.x;
    const float* xn = x0 + (size_t)node * NODE_SZ;
#pragma unroll
    for (int it = 0; it < 15; it++)
        lin[tid + (it << 9)] = xn[tid + (it << 9)];
    __syncthreads();
    frag_convert(lin, FH, FL, tid);
    __syncthreads();
    mma_node(FH, FL, 0, node, tid, g_y[0]);
}

// ---------------- F_l: edge(l) single-pass-LN [+ gemm(l+1) in-CTA] ------------
__global__ __launch_bounds__(512, 2)
void fused_kernel(const float* __restrict__ ea,
                  const float* __restrict__ lng,
                  const float* __restrict__ lnb,
                  const int* __restrict__ ei,
                  float* __restrict__ dout, int l) {
    extern __shared__ float sm[];
    float* lin = sm;                                         // [0, NODE_SZ)
    unsigned* FH = reinterpret_cast<unsigned*>(sm + NODE_SZ);
    unsigned* FL = FH + 4096;
    float* es_all = reinterpret_cast<float*>(FH);            // aliases FH (dead by MMA)
    __shared__ float red[8][32];                             // per-edge reduction slots

    int n = blockIdx.x, tid = threadIdx.x;
    const float* ybuf = g_y[l & 1];
    int deg = g_deg[n];
    int notok = g_notok[l];

    const float* yan = ybuf + (size_t)(2 * n) * NODE_SZ;
    float ya[15], acc[15];
#pragma unroll
    for (int it = 0; it < 15; it++) {
        ya[it] = __ldg(yan + tid + (it << 9));
        acc[it] = 0.f;
    }
    for (int idx = tid; idx < deg * CCH; idx += 512) {
        int j = idx >> 7, c = idx & 127;
        int e = g_nbr[n * 16 + j];
        const float* Mp = g_M + l * (CCH * 6) + c * 6;
        const float* eap = ea + e * 5;
        es_all[idx] = fmaf(Mp[0], eap[0], fmaf(Mp[1], eap[1], fmaf(Mp[2], eap[2],
                      fmaf(Mp[3], eap[3], fmaf(Mp[4], eap[4], Mp[5])))));
    }
    __syncthreads();   // es_all visible

    for (int j = 0; j < deg; j++) {
        int e = g_nbr[n * 16 + j];
        int s = ei[e];
        const float* yb = ybuf + (size_t)(2 * s + 1) * NODE_SZ;
        const float* esj = es_all + j * CCH;

        float t[15];
        float s1 = 0.f, s2 = 0.f;
#pragma unroll
        for (int it = 0; it < 15; it++) {
            int i = tid + (it << 9);
            float v = ya[it] + __ldg(yb + i) + esj[i / HEIGHT];
            t[it] = v;
            s1 += v;
            s2 += v * v;
        }
#pragma unroll
        for (int o = 16; o; o >>= 1) {
            s1 += __shfl_xor_sync(0xffffffffu, s1, o);
            s2 += __shfl_xor_sync(0xffffffffu, s2, o);
        }
        if ((tid & 31) == 0) { red[j][tid >> 5] = s1; red[j][16 + (tid >> 5)] = s2; }
        __syncthreads();   // the ONLY barrier per edge
        float a = 0.f, b2 = 0.f;
#pragma unroll
        for (int w = 0; w < 16; w++) { a += red[j][w]; b2 += red[j][16 + w]; }
        float mu = a * (1.f / (float)NODE_SZ);
        float rs = rsqrtf(b2 * (1.f / (float)NODE_SZ) - mu * mu + 1e-5f);
        if (!notok) {
            // fast path: gl==1, bl==0 -> relu((v-mu)*rs) = rs*max(v-mu,0)
#pragma unroll
            for (int it = 0; it < 15; it++)
                acc[it] = fmaf(rs, fmaxf(t[it] - mu, 0.f), acc[it]);
        } else {
            const float* gl = lng + l * NODE_SZ;
            const float* bl = lnb + l * NODE_SZ;
#pragma unroll
            for (int it = 0; it < 15; it++) {
                int i = tid + (it << 9);
                float o2 = (t[it] - mu) * rs * __ldg(gl + i) + __ldg(bl + i);
                acc[it] += fmaxf(o2, 0.f);
            }
        }
    }

    if (l == 3) {
        float* on = dout + (size_t)n * NODE_SZ;
#pragma unroll
        for (int it = 0; it < 15; it++)
            on[tid + (it << 9)] = acc[it];
        return;
    }

    // ---- in-CTA gemm(l+1): acc -> lin -> B frags (smem) -> MMA -> buf (l+1)&1 -
    __syncthreads();              // es_all reads complete before FH overwrite
#pragma unroll
    for (int it = 0; it < 15; it++)
        lin[tid + (it << 9)] = acc[it];
    __syncthreads();
    frag_convert(lin, FH, FL, tid);
    __syncthreads();
    mma_node(FH, FL, l + 1, n, tid, g_y[(l + 1) & 1]);
}

// ---------------- launch -----------------------------------------------------
extern "C" void kernel_launch(void* const* d_in, const int* in_sizes, int n_in,
                              void* d_out, int out_size) {
    const float* x   = (const float*)d_in[0];
    const float* ea  = (const float*)d_in[1];
    const float* ew  = (const float*)d_in[2];
    const float* eb  = (const float*)d_in[3];
    const float* cw  = (const float*)d_in[4];
    const float* lng = (const float*)d_in[5];
    const float* lnb = (const float*)d_in[6];
    const int*   ei  = (const int*)d_in[7];
    float* out = (float*)d_out;
    int E = in_sizes[7] / 2;

    cudaFuncSetAttribute(gemm0_kernel, cudaFuncAttributeMaxDynamicSharedMemorySize, DYN_SMEM);
    cudaFuncSetAttribute(fused_kernel, cudaFuncAttributeMaxDynamicSharedMemorySize, DYN_SMEM);

    setup_kernel<<<5, 384>>>(ei, E, cw, ew, eb, lng, lnb);
    gemm0_kernel<<<N_NODES, 512, DYN_SMEM>>>(x);
    for (int l = 0; l < N_LAYERS; l++)
        fused_kernel<<<N_NODES, 512, DYN_SMEM>>>(ea, lng, lnb, ei, out, l);
}